// round 11
// baseline (speedup 1.0000x reference)
#include <cuda_runtime.h>
#include <cuda_bf16.h>
#include <cuda_fp8.h>
#include <cstdint>

#define NROWS 8192
#define DIM   512
#define SCALE 2.659f
#define QS    64.0f             // fp8 quantization scale
#define INVQ2 (1.0f / 4096.0f)  // 1/(QS*QS)

__device__ uint8_t g_img8[NROWS * DIM];
__device__ uint8_t g_txt8[NROWS * DIM];
__device__ int   g_key[NROWS];
__device__ float g_cnt[NROWS];
__device__ float g_rowsum[NROWS];
__device__ float g_rowdot[NROWS];
__device__ float g_colsum[NROWS];
__device__ float g_coldot[NROWS];
__device__ float g_csum_txt[128 * DIM];
__device__ float g_csum_img[128 * DIM];
__device__ int   g_done;

// ---------------- asm helpers ----------------
#define MMA_FP8(C, A, B0, B1)                                                \
    asm volatile(                                                            \
        "mma.sync.aligned.m16n8k32.row.col.f32.e4m3.e4m3.f32 "               \
        "{%0,%1,%2,%3}, {%4,%5,%6,%7}, {%8,%9}, {%0,%1,%2,%3};"              \
        : "+f"((C)[0]), "+f"((C)[1]), "+f"((C)[2]), "+f"((C)[3])             \
        : "r"((A)[0]), "r"((A)[1]), "r"((A)[2]), "r"((A)[3]),                \
          "r"(B0), "r"(B1))

#define LDSM4(R, ADDR)                                                       \
    asm volatile("ldmatrix.sync.aligned.m8n8.x4.shared.b16 {%0,%1,%2,%3}, [%4];" \
                 : "=r"((R)[0]), "=r"((R)[1]), "=r"((R)[2]), "=r"((R)[3])    \
                 : "r"(ADDR))

#define CP_ASYNC16(dst, src)                                                 \
    asm volatile("cp.async.cg.shared.global [%0], [%1], 16;"                 \
                 :: "r"(dst), "l"(src))
#define CP_COMMIT() asm volatile("cp.async.commit_group;" ::: "memory")
#define CP_WAIT(N)  asm volatile("cp.async.wait_group %0;" :: "n"(N) : "memory")

__device__ __forceinline__ uint32_t pack_e4m3x4(float a, float b, float c, float d) {
    uint16_t lo, hi;
    asm("cvt.rn.satfinite.e4m3x2.f32 %0, %1, %2;" : "=h"(lo) : "f"(b), "f"(a));
    asm("cvt.rn.satfinite.e4m3x2.f32 %0, %1, %2;" : "=h"(hi) : "f"(d), "f"(c));
    return (uint32_t)lo | ((uint32_t)hi << 16);
}

__device__ __forceinline__ float4 fp8x4_to_float4(uint32_t v) {
    __half2_raw lo = __nv_cvt_fp8x2_to_halfraw2((__nv_fp8x2_storage_t)(v & 0xFFFFu), __NV_E4M3);
    __half2_raw hi = __nv_cvt_fp8x2_to_halfraw2((__nv_fp8x2_storage_t)(v >> 16), __NV_E4M3);
    __half2 l = *reinterpret_cast<__half2*>(&lo);
    __half2 h = *reinterpret_cast<__half2*>(&hi);
    return make_float4(__low2float(l), __high2float(l),
                       __low2float(h), __high2float(h));
}

// ---------------------------------------------------------------------------
// Prep kernel: grid (NROWS+1, 2), 128 threads.
//   blockIdx.x < NROWS  -> L2-normalize one row, quantize to e4m3 (x * 64).
//   blockIdx.x == NROWS, y == 0 -> label prep.
// ---------------------------------------------------------------------------
__global__ void prep_kernel(const float* __restrict__ text,
                            const float* __restrict__ image,
                            const int* __restrict__ p) {
    int tid = threadIdx.x;
    if (blockIdx.x == NROWS) {
        if (blockIdx.y != 0) return;
        __shared__ int viol;
        __shared__ int h[128];
        if (tid == 0) { viol = 0; g_done = 0; }
        h[tid] = 0;
        __syncthreads();
        int v = 0;
        for (int i = tid; i < NROWS / 2; i += 128) {
            int hiw = p[2 * i + 1];
            if (hiw != 0 && hiw != -1) v = 1;
        }
        if (v) atomicAdd(&viol, 1);
        __syncthreads();
        bool is64 = (viol == 0);
        for (int i = tid; i < NROWS; i += 128) {
            int l = is64 ? p[2 * i] : p[i];
            g_key[i] = (l >= 0 && l < 128) ? l : (1 << 20) + i;
            if (l >= 0 && l < 128) atomicAdd(&h[l], 1);
            g_rowsum[i] = 0.0f;
            g_colsum[i] = 0.0f;
        }
        __syncthreads();
        for (int i = tid; i < NROWS; i += 128) {
            int k = g_key[i];
            g_cnt[i] = (k < 128) ? (float)h[k] : 1.0f;
        }
        return;
    }

    int row = blockIdx.x;
    const float* src = blockIdx.y ? text : image;
    uint8_t* dst = blockIdx.y ? g_txt8 : g_img8;
    int lane = tid & 31, wid = tid >> 5;

    float4 v = ((const float4*)(src + (size_t)row * DIM))[tid];
    float ss = v.x * v.x + v.y * v.y + v.z * v.z + v.w * v.w;
#pragma unroll
    for (int o = 16; o; o >>= 1) ss += __shfl_xor_sync(0xffffffffu, ss, o);
    __shared__ float wss[4];
    if (lane == 0) wss[wid] = ss;
    __syncthreads();
    float tot = wss[0] + wss[1] + wss[2] + wss[3];
    float inv = QS / fmaxf(sqrtf(tot), 1e-12f);

    ((uint32_t*)(dst + (size_t)row * DIM))[tid] =
        pack_e4m3x4(v.x * inv, v.y * inv, v.z * inv, v.w * inv);
}

// ---------------------------------------------------------------------------
// Class-sum kernel: block k (0..127) computes C_k = sum of quantized txt rows
// in class k and D_k = sum of quantized img rows. Deterministic per class.
// ---------------------------------------------------------------------------
__global__ void csum_kernel() {
    __shared__ int mlist[8192];
    __shared__ int mcnt;
    int k = blockIdx.x, tid = threadIdx.x;
    if (tid == 0) mcnt = 0;
    __syncthreads();
    for (int i = tid; i < NROWS; i += 256)
        if (g_key[i] == k) mlist[atomicAdd(&mcnt, 1)] = i;
    __syncthreads();
    int cnt = mcnt;
    float t0 = 0.f, t1 = 0.f, u0 = 0.f, u1 = 0.f;
    for (int m = 0; m < cnt; m++) {
        int r = mlist[m];
        uint16_t a = *(const uint16_t*)(g_txt8 + (size_t)r * DIM + 2 * tid);
        uint16_t b = *(const uint16_t*)(g_img8 + (size_t)r * DIM + 2 * tid);
        __half2_raw ha = __nv_cvt_fp8x2_to_halfraw2(a, __NV_E4M3);
        __half2_raw hb = __nv_cvt_fp8x2_to_halfraw2(b, __NV_E4M3);
        __half2 h2a = *reinterpret_cast<__half2*>(&ha);
        __half2 h2b = *reinterpret_cast<__half2*>(&hb);
        t0 += __low2float(h2a); t1 += __high2float(h2a);
        u0 += __low2float(h2b); u1 += __high2float(h2b);
    }
    g_csum_txt[k * DIM + 2 * tid]     = t0;
    g_csum_txt[k * DIM + 2 * tid + 1] = t1;
    g_csum_img[k * DIM + 2 * tid]     = u0;
    g_csum_img[k * DIM + 2 * tid + 1] = u1;
}

// ---------------------------------------------------------------------------
// Dot kernel: rowdot_i = x_i . C_{key_i} (labeled) or x_i . y_i (unlabeled),
// coldot likewise. Units: QS^2 * true-dot (matches finale scaling).
// grid 64 x 256 threads (8 warps); each warp handles 16 rows, both dirs.
// ---------------------------------------------------------------------------
__global__ void dot_kernel() {
    int tid = threadIdx.x, lane = tid & 31, w = tid >> 5;
    int base = blockIdx.x * 128 + w * 16;
    for (int rr = 0; rr < 16; rr++) {
        int row = base + rr;
        int key = g_key[row];
        const uint32_t* xa = (const uint32_t*)(g_img8 + (size_t)row * DIM) + lane * 4;
        const uint32_t* ya = (const uint32_t*)(g_txt8 + (size_t)row * DIM) + lane * 4;
        float s = 0.f, t = 0.f;
        if (key < 128) {
            const float4* Ct = (const float4*)(g_csum_txt + key * DIM) + lane * 4;
            const float4* Ci = (const float4*)(g_csum_img + key * DIM) + lane * 4;
#pragma unroll
            for (int q = 0; q < 4; q++) {
                float4 xf = fp8x4_to_float4(xa[q]);
                float4 yf = fp8x4_to_float4(ya[q]);
                float4 cf = Ct[q];
                float4 df = Ci[q];
                s += xf.x * cf.x + xf.y * cf.y + xf.z * cf.z + xf.w * cf.w;
                t += yf.x * df.x + yf.y * df.y + yf.z * df.z + yf.w * df.w;
            }
        } else {
#pragma unroll
            for (int q = 0; q < 4; q++) {
                float4 xf = fp8x4_to_float4(xa[q]);
                float4 yf = fp8x4_to_float4(ya[q]);
                s += xf.x * yf.x + xf.y * yf.y + xf.z * yf.z + xf.w * yf.w;
            }
            t = s;   // resolved after reduction identically
        }
#pragma unroll
        for (int o = 16; o; o >>= 1) {
            s += __shfl_xor_sync(0xffffffffu, s, o);
            t += __shfl_xor_sync(0xffffffffu, t, o);
        }
        if (lane == 0) { g_rowdot[row] = s; g_coldot[row] = t; }
    }
}

// ---------------------------------------------------------------------------
// Main kernel: single pass over S = img_n @ txt_n^T in fp8 (e4m3).
// grid (64, 64), 256 threads (8 warps = 4m x 2n), warp tile 32x64,
// CTA tile 128 x 128, two CTAs co-resident per SM. Epilogue is dot-free:
// only exp accumulation (the target-dot is computed analytically upstream).
// ---------------------------------------------------------------------------
__global__ __launch_bounds__(256, 2)
void unicl_gemm_kernel(float* __restrict__ out) {
    extern __shared__ char sm[];
    uint32_t sbase = (uint32_t)__cvta_generic_to_shared(sm);
    const uint32_t As_u = sbase;                // [4 kc][128 rows][128 B]
    const uint32_t Bs_u = sbase + 65536u;       // 2 stages x [128 cols][128 B]
    float* row_se = (float*)(sm + 98304);       // 128
    float* col_se = (float*)(sm + 98816);       // 128
    int*   flag_s = (int*)(sm + 99328);
    float* red_s  = (float*)(sm + 99328);       // 256 floats (reuse)

    int tid = threadIdx.x, lane = tid & 31, wid = tid >> 5;
    int gm0 = blockIdx.x * 128;
    int n0  = blockIdx.y * 128;
    const uint8_t* Ag = g_img8;
    const uint8_t* Bg = g_txt8;

    for (int i = tid; i < 128; i += 256) { row_se[i] = 0.0f; col_se[i] = 0.0f; }

    // --- A prologue: 128x512B into [kc][128][128B] swizzled ---
#pragma unroll
    for (int q = 0; q < 16; q++) {
        int idx = tid + q * 256;
        int kc = idx >> 10, row = (idx >> 3) & 127, ch = idx & 7;
        const void* src = Ag + (size_t)(gm0 + row) * DIM + kc * 128 + ch * 16;
        uint32_t dst = As_u + kc * 16384 + row * 128 + ((ch ^ (row & 7)) << 4);
        CP_ASYNC16(dst, src);
    }
    CP_COMMIT();

    auto issueB = [&](int kc) {
        const uint8_t* bsrc = Bg + (size_t)n0 * DIM + kc * 128;
        uint32_t bdst = Bs_u + (uint32_t)(kc & 1) * 16384u;
#pragma unroll
        for (int q = 0; q < 4; q++) {
            int idx = tid + q * 256;
            int row = idx >> 3, ch = idx & 7;
            CP_ASYNC16(bdst + row * 128 + ((ch ^ (row & 7)) << 4),
                       bsrc + (size_t)row * DIM + ch * 16);
        }
    };
    issueB(0); CP_COMMIT();

    // --- warp geometry: 4 m-warps (32 rows) x 2 n-warps (64 cols) ---
    int warp_m = (wid & 3) * 32;
    int warp_n = (wid >> 2) * 64;
    int g = lane >> 2, tig = lane & 3;
    uint32_t a_off = (uint32_t)(warp_m + (lane & 15)) * 128;
    uint32_t hiA = (uint32_t)(lane >> 4);
    uint32_t swA = (uint32_t)(lane & 7);
    int rB0 = warp_n + (lane & 7) + ((lane >> 4) << 3);
    uint32_t b_off = (uint32_t)rB0 * 128;
    uint32_t hiB = (uint32_t)((lane >> 3) & 1);
    uint32_t swB = (uint32_t)(lane & 7);

    float rse[4] = {0.f, 0.f, 0.f, 0.f};
    const float K2q = SCALE * 1.44269504f * INVQ2;
    const float K2b = SCALE * 1.44269504f;

    float c[2][8][4];
#pragma unroll
    for (int mf = 0; mf < 2; mf++)
#pragma unroll
        for (int nf = 0; nf < 8; nf++)
#pragma unroll
            for (int e = 0; e < 4; e++) c[mf][nf][e] = 0.0f;

#pragma unroll 1
    for (int kc = 0; kc < 4; kc++) {
        CP_WAIT(0);
        __syncthreads();   // all warps done with prior chunk -> other stage free
        if (kc + 1 < 4) { issueB(kc + 1); CP_COMMIT(); }

        uint32_t Ab = As_u + kc * 16384;
        uint32_t Bb = Bs_u + (uint32_t)(kc & 1) * 16384u;
#pragma unroll
        for (int k32 = 0; k32 < 4; k32++) {
            uint32_t a0[4], a1[4], b[4][4];
            uint32_t cA = ((k32 * 2 + hiA) ^ swA) << 4;
            LDSM4(a0, Ab + a_off + cA);
            LDSM4(a1, Ab + a_off + 2048 + cA);
            uint32_t cB = ((k32 * 2 + hiB) ^ swB) << 4;
            LDSM4(b[0], Bb + b_off + cB);
            LDSM4(b[1], Bb + b_off + 2048 + cB);
            LDSM4(b[2], Bb + b_off + 4096 + cB);
            LDSM4(b[3], Bb + b_off + 6144 + cB);
#pragma unroll
            for (int j = 0; j < 4; j++) {
                MMA_FP8(c[0][2 * j],     a0, b[j][0], b[j][1]);
                MMA_FP8(c[0][2 * j + 1], a0, b[j][2], b[j][3]);
                MMA_FP8(c[1][2 * j],     a1, b[j][0], b[j][1]);
                MMA_FP8(c[1][2 * j + 1], a1, b[j][2], b[j][3]);
            }
        }
    }

    // --- epilogue: exp accumulation only ---
    float cse[16];
#pragma unroll
    for (int p = 0; p < 16; p++) cse[p] = 0.0f;
#pragma unroll
    for (int mf = 0; mf < 2; mf++) {
#pragma unroll
        for (int nf = 0; nf < 8; nf++) {
#pragma unroll
            for (int e = 0; e < 4; e++) {
                float ex;
                asm("ex2.approx.ftz.f32 %0, %1;" : "=f"(ex)
                    : "f"(fmaf(c[mf][nf][e], K2q, -K2b)));
                rse[mf * 2 + (e >> 1)] += ex;
                cse[nf * 2 + (e & 1)]  += ex;
            }
        }
    }
#pragma unroll
    for (int p = 0; p < 16; p++) {
        cse[p] += __shfl_xor_sync(0xffffffffu, cse[p], 4);
        cse[p] += __shfl_xor_sync(0xffffffffu, cse[p], 8);
        cse[p] += __shfl_xor_sync(0xffffffffu, cse[p], 16);
    }
#pragma unroll
    for (int q = 0; q < 2; q++) {
        int p = g * 2 + q;
        int cidx = warp_n + (p >> 1) * 8 + tig * 2 + (p & 1);
        atomicAdd(&col_se[cidx], cse[p]);
    }
#pragma unroll
    for (int ri = 0; ri < 4; ri++) {
        float v = rse[ri];
        v += __shfl_xor_sync(0xffffffffu, v, 1);
        v += __shfl_xor_sync(0xffffffffu, v, 2);
        if (tig == 0) atomicAdd(&row_se[warp_m + g + ri * 8], v);
    }
    __syncthreads();
    for (int i = tid; i < 128; i += 256) {
        atomicAdd(&g_rowsum[gm0 + i], row_se[i]);
        atomicAdd(&g_colsum[n0 + i], col_se[i]);
    }

    // --- last CTA computes the final loss ---
    __threadfence();
    __syncthreads();
    if (tid == 0) {
        int prev = atomicAdd(&g_done, 1);
        flag_s[0] = (prev == gridDim.x * gridDim.y - 1) ? 1 : 0;
    }
    __syncthreads();
    if (flag_s[0]) {
        __threadfence();
        float s = 0.0f;
        for (int i = tid; i < NROWS; i += 256) {
            float inv = (SCALE * INVQ2) / g_cnt[i];
            s += 2.0f * SCALE + logf(g_rowsum[i]) + logf(g_colsum[i])
                 - (g_rowdot[i] + g_coldot[i]) * inv;
        }
        __syncthreads();
        red_s[tid] = s;
        __syncthreads();
        for (int o = 128; o; o >>= 1) {
            if (tid < o) red_s[tid] += red_s[tid + o];
            __syncthreads();
        }
        if (tid == 0) out[0] = red_s[0] * (1.0f / (2.0f * NROWS));
    }
}

// ---------------------------------------------------------------------------
extern "C" void kernel_launch(void* const* d_in, const int* in_sizes, int n_in,
                              void* d_out, int out_size) {
    const float* text   = (const float*)d_in[0];
    const float* image  = (const float*)d_in[1];
    const int*   labels = (const int*)d_in[2];
    float* out = (float*)d_out;

    prep_kernel<<<dim3(NROWS + 1, 2), 128>>>(text, image, labels);
    csum_kernel<<<128, 256>>>();
    dot_kernel<<<64, 256>>>();

    int smem_bytes = 100352;
    cudaFuncSetAttribute(unicl_gemm_kernel,
                         cudaFuncAttributeMaxDynamicSharedMemorySize, smem_bytes);
    unicl_gemm_kernel<<<dim3(64, 64), 256, smem_bytes>>>(out);
}

// round 12
// speedup vs baseline: 1.0628x; 1.0628x over previous
#include <cuda_runtime.h>
#include <cuda_bf16.h>
#include <cuda_fp8.h>
#include <cstdint>

#define NROWS 8192
#define DIM   512
#define SCALE 2.659f
#define QS    64.0f             // fp8 quantization scale
#define INVQ2 (1.0f / 4096.0f)  // 1/(QS*QS)
#define NTILES 4096             // 64 m-blocks x 64 n-blocks of 128x128

__device__ uint8_t g_img8[NROWS * DIM];
__device__ uint8_t g_txt8[NROWS * DIM];
__device__ int   g_key[NROWS];
__device__ float g_cnt[NROWS];
__device__ float g_rowsum[NROWS];
__device__ float g_rowdot[NROWS];
__device__ float g_colsum[NROWS];
__device__ float g_coldot[NROWS];
__device__ float g_csum_txt[128 * DIM];
__device__ float g_csum_img[128 * DIM];
__device__ int   g_done;

// ---------------- asm helpers ----------------
#define MMA_FP8(C, A, B0, B1)                                                \
    asm volatile(                                                            \
        "mma.sync.aligned.m16n8k32.row.col.f32.e4m3.e4m3.f32 "               \
        "{%0,%1,%2,%3}, {%4,%5,%6,%7}, {%8,%9}, {%0,%1,%2,%3};"              \
        : "+f"((C)[0]), "+f"((C)[1]), "+f"((C)[2]), "+f"((C)[3])             \
        : "r"((A)[0]), "r"((A)[1]), "r"((A)[2]), "r"((A)[3]),                \
          "r"(B0), "r"(B1))

#define LDSM4(R, ADDR)                                                       \
    asm volatile("ldmatrix.sync.aligned.m8n8.x4.shared.b16 {%0,%1,%2,%3}, [%4];" \
                 : "=r"((R)[0]), "=r"((R)[1]), "=r"((R)[2]), "=r"((R)[3])    \
                 : "r"(ADDR))

#define CP_ASYNC16(dst, src)                                                 \
    asm volatile("cp.async.cg.shared.global [%0], [%1], 16;"                 \
                 :: "r"(dst), "l"(src))
#define CP_COMMIT() asm volatile("cp.async.commit_group;" ::: "memory")
#define CP_WAIT(N)  asm volatile("cp.async.wait_group %0;" :: "n"(N) : "memory")

__device__ __forceinline__ uint32_t pack_e4m3x4(float a, float b, float c, float d) {
    uint16_t lo, hi;
    asm("cvt.rn.satfinite.e4m3x2.f32 %0, %1, %2;" : "=h"(lo) : "f"(b), "f"(a));
    asm("cvt.rn.satfinite.e4m3x2.f32 %0, %1, %2;" : "=h"(hi) : "f"(d), "f"(c));
    return (uint32_t)lo | ((uint32_t)hi << 16);
}

__device__ __forceinline__ float4 fp8x4_to_float4(uint32_t v) {
    __half2_raw lo = __nv_cvt_fp8x2_to_halfraw2((__nv_fp8x2_storage_t)(v & 0xFFFFu), __NV_E4M3);
    __half2_raw hi = __nv_cvt_fp8x2_to_halfraw2((__nv_fp8x2_storage_t)(v >> 16), __NV_E4M3);
    __half2 l = *reinterpret_cast<__half2*>(&lo);
    __half2 h = *reinterpret_cast<__half2*>(&hi);
    return make_float4(__low2float(l), __high2float(l),
                       __low2float(h), __high2float(h));
}

// ---------------------------------------------------------------------------
// Prep kernel: grid (NROWS+1, 2), 128 threads.
// ---------------------------------------------------------------------------
__global__ void prep_kernel(const float* __restrict__ text,
                            const float* __restrict__ image,
                            const int* __restrict__ p) {
    int tid = threadIdx.x;
    if (blockIdx.x == NROWS) {
        if (blockIdx.y != 0) return;
        __shared__ int viol;
        __shared__ int h[128];
        if (tid == 0) { viol = 0; g_done = 0; }
        h[tid] = 0;
        __syncthreads();
        int v = 0;
        for (int i = tid; i < NROWS / 2; i += 128) {
            int hiw = p[2 * i + 1];
            if (hiw != 0 && hiw != -1) v = 1;
        }
        if (v) atomicAdd(&viol, 1);
        __syncthreads();
        bool is64 = (viol == 0);
        for (int i = tid; i < NROWS; i += 128) {
            int l = is64 ? p[2 * i] : p[i];
            g_key[i] = (l >= 0 && l < 128) ? l : (1 << 20) + i;
            if (l >= 0 && l < 128) atomicAdd(&h[l], 1);
            g_rowsum[i] = 0.0f;
            g_colsum[i] = 0.0f;
        }
        __syncthreads();
        for (int i = tid; i < NROWS; i += 128) {
            int k = g_key[i];
            g_cnt[i] = (k < 128) ? (float)h[k] : 1.0f;
        }
        return;
    }

    int row = blockIdx.x;
    const float* src = blockIdx.y ? text : image;
    uint8_t* dst = blockIdx.y ? g_txt8 : g_img8;
    int lane = tid & 31, wid = tid >> 5;

    float4 v = ((const float4*)(src + (size_t)row * DIM))[tid];
    float ss = v.x * v.x + v.y * v.y + v.z * v.z + v.w * v.w;
#pragma unroll
    for (int o = 16; o; o >>= 1) ss += __shfl_xor_sync(0xffffffffu, ss, o);
    __shared__ float wss[4];
    if (lane == 0) wss[wid] = ss;
    __syncthreads();
    float tot = wss[0] + wss[1] + wss[2] + wss[3];
    float inv = QS / fmaxf(sqrtf(tot), 1e-12f);

    ((uint32_t*)(dst + (size_t)row * DIM))[tid] =
        pack_e4m3x4(v.x * inv, v.y * inv, v.z * inv, v.w * inv);
}

// ---------------------------------------------------------------------------
// Class-sum kernel: 256 blocks (class k = b>>1, dir = b&1), 512 threads.
// LUT-based fp8 decode, 4-way ILP over member rows.
// ---------------------------------------------------------------------------
__global__ void csum_kernel() {
    __shared__ float tbl[256];
    __shared__ int mlist[8192];
    __shared__ int mcnt;
    int k = blockIdx.x >> 1, dir = blockIdx.x & 1;
    const uint8_t* src = dir ? g_img8 : g_txt8;
    float* dst = dir ? g_csum_img : g_csum_txt;
    int tid = threadIdx.x;
    if (tid == 0) mcnt = 0;
    if (tid < 256) {
        __half_raw hr = __nv_cvt_fp8_to_halfraw((__nv_fp8_storage_t)tid, __NV_E4M3);
        tbl[tid] = __half2float(*reinterpret_cast<__half*>(&hr));
    }
    __syncthreads();
    for (int i = tid; i < NROWS; i += 512)
        if (g_key[i] == k) mlist[atomicAdd(&mcnt, 1)] = i;
    __syncthreads();
    int cnt = mcnt;
    float a0 = 0.f, a1 = 0.f, a2 = 0.f, a3 = 0.f;
    int m = 0;
    for (; m + 4 <= cnt; m += 4) {
        a0 += tbl[src[(size_t)mlist[m]     * DIM + tid]];
        a1 += tbl[src[(size_t)mlist[m + 1] * DIM + tid]];
        a2 += tbl[src[(size_t)mlist[m + 2] * DIM + tid]];
        a3 += tbl[src[(size_t)mlist[m + 3] * DIM + tid]];
    }
    for (; m < cnt; m++) a0 += tbl[src[(size_t)mlist[m] * DIM + tid]];
    dst[k * DIM + tid] = (a0 + a1) + (a2 + a3);
}

// ---------------------------------------------------------------------------
// Dot kernel: rowdot_i = x_i . C_{key_i} (labeled) or x_i . y_i (unlabeled).
// ---------------------------------------------------------------------------
__global__ void dot_kernel() {
    int tid = threadIdx.x, lane = tid & 31, w = tid >> 5;
    int base = blockIdx.x * 128 + w * 16;
    for (int rr = 0; rr < 16; rr++) {
        int row = base + rr;
        int key = g_key[row];
        const uint32_t* xa = (const uint32_t*)(g_img8 + (size_t)row * DIM) + lane * 4;
        const uint32_t* ya = (const uint32_t*)(g_txt8 + (size_t)row * DIM) + lane * 4;
        float s = 0.f, t = 0.f;
        if (key < 128) {
            const float4* Ct = (const float4*)(g_csum_txt + key * DIM) + lane * 4;
            const float4* Ci = (const float4*)(g_csum_img + key * DIM) + lane * 4;
#pragma unroll
            for (int q = 0; q < 4; q++) {
                float4 xf = fp8x4_to_float4(xa[q]);
                float4 yf = fp8x4_to_float4(ya[q]);
                float4 cf = Ct[q];
                float4 df = Ci[q];
                s += xf.x * cf.x + xf.y * cf.y + xf.z * cf.z + xf.w * cf.w;
                t += yf.x * df.x + yf.y * df.y + yf.z * df.z + yf.w * df.w;
            }
        } else {
#pragma unroll
            for (int q = 0; q < 4; q++) {
                float4 xf = fp8x4_to_float4(xa[q]);
                float4 yf = fp8x4_to_float4(ya[q]);
                s += xf.x * yf.x + xf.y * yf.y + xf.z * yf.z + xf.w * yf.w;
            }
            t = s;
        }
#pragma unroll
        for (int o = 16; o; o >>= 1) {
            s += __shfl_xor_sync(0xffffffffu, s, o);
            t += __shfl_xor_sync(0xffffffffu, t, o);
        }
        if (lane == 0) { g_rowdot[row] = s; g_coldot[row] = t; }
    }
}

// ---------------------------------------------------------------------------
// Main kernel: PERSISTENT CTAs, static contiguous tile schedule (m-major).
// grid = 2 x SMs, 256 threads (8 warps = 4m x 2n), tile 128x128.
// Each CTA: contiguous tile range; A panel reloaded only at m-change (<=2x);
// B 2-stage cp.async ring pipelined continuously across tile boundaries.
// Row stats live in registers across same-m tiles; col stats flushed per tile
// by direct global atomics. Last CTA computes the final loss.
// ---------------------------------------------------------------------------
__global__ __launch_bounds__(256, 2)
void unicl_gemm_kernel(float* __restrict__ out) {
    extern __shared__ char sm[];
    uint32_t sbase = (uint32_t)__cvta_generic_to_shared(sm);
    const uint32_t As_u = sbase;                // [4 kc][128 rows][128 B]
    const uint32_t Bs_u = sbase + 65536u;       // 2 stages x [128 cols][128 B]
    int*   flag_s = (int*)(sm + 98304);
    float* red_s  = (float*)(sm + 98304);       // 256 floats (reuse)

    int tid = threadIdx.x, lane = tid & 31, wid = tid >> 5;
    const uint8_t* Ag = g_img8;
    const uint8_t* Bg = g_txt8;

    // --- static schedule ---
    int G = gridDim.x;
    int base = NTILES / G, rem = NTILES % G;
    int c_ = blockIdx.x;
    int ts = c_ * base + min(c_, rem);
    int cnt = base + (c_ < rem ? 1 : 0);
    int total_chunks = cnt * 4;

    // --- warp geometry: 4 m-warps (32 rows) x 2 n-warps (64 cols) ---
    int warp_m = (wid & 3) * 32;
    int warp_n = (wid >> 2) * 64;
    int g = lane >> 2, tig = lane & 3;
    uint32_t a_off = (uint32_t)(warp_m + (lane & 15)) * 128;
    uint32_t hiA = (uint32_t)(lane >> 4);
    uint32_t swA = (uint32_t)(lane & 7);
    int rB0 = warp_n + (lane & 7) + ((lane >> 4) << 3);
    uint32_t b_off = (uint32_t)rB0 * 128;
    uint32_t hiB = (uint32_t)((lane >> 3) & 1);
    uint32_t swB = (uint32_t)(lane & 7);

    const float K2q = SCALE * 1.44269504f * INVQ2;
    const float K2b = SCALE * 1.44269504f;

    auto issueB = [&](int n0, int kc, int stage) {
        const uint8_t* bsrc = Bg + (size_t)n0 * DIM + kc * 128;
        uint32_t bdst = Bs_u + (uint32_t)stage * 16384u;
#pragma unroll
        for (int q = 0; q < 4; q++) {
            int idx = tid + q * 256;
            int row = idx >> 3, ch = idx & 7;
            CP_ASYNC16(bdst + row * 128 + ((ch ^ (row & 7)) << 4),
                       bsrc + (size_t)row * DIM + ch * 16);
        }
    };

    float rse[4] = {0.f, 0.f, 0.f, 0.f};
    int curm = -1;
    int cc = 0;

    if (cnt > 0) { issueB(((ts & 63) << 7), 0, 0); CP_COMMIT(); }

    for (int ti = ts; ti < ts + cnt; ti++) {
        int m = ti >> 6, n = ti & 63;
        int gm0 = m << 7, n0 = n << 7;

        if (m != curm) {
            if (curm >= 0) {
                int pg = curm << 7;
#pragma unroll
                for (int ri = 0; ri < 4; ri++) {
                    float v = rse[ri];
                    v += __shfl_xor_sync(0xffffffffu, v, 1);
                    v += __shfl_xor_sync(0xffffffffu, v, 2);
                    if (tig == 0)
                        atomicAdd(&g_rowsum[pg + warp_m + g + ri * 8], v);
                    rse[ri] = 0.0f;
                }
            }
            __syncthreads();   // all warps done reading old A
#pragma unroll
            for (int q = 0; q < 16; q++) {
                int idx = tid + q * 256;
                int kc2 = idx >> 10, row = (idx >> 3) & 127, ch = idx & 7;
                const void* src = Ag + (size_t)(gm0 + row) * DIM + kc2 * 128 + ch * 16;
                uint32_t dst = As_u + kc2 * 16384 + row * 128 + ((ch ^ (row & 7)) << 4);
                CP_ASYNC16(dst, src);
            }
            CP_COMMIT();
            curm = m;
        }

        float c[2][8][4];
#pragma unroll
        for (int mf = 0; mf < 2; mf++)
#pragma unroll
            for (int nf = 0; nf < 8; nf++)
#pragma unroll
                for (int e = 0; e < 4; e++) c[mf][nf][e] = 0.0f;

#pragma unroll 1
        for (int kc = 0; kc < 4; kc++) {
            CP_WAIT(0);
            __syncthreads();   // chunk cc ready; other stage reusable
            int nxt = cc + 1;
            if (nxt < total_chunks) {
                int nti = ts + (nxt >> 2);
                issueB(((nti & 63) << 7), nxt & 3, nxt & 1);
                CP_COMMIT();
            }
            uint32_t Ab = As_u + kc * 16384;
            uint32_t Bb = Bs_u + (uint32_t)(cc & 1) * 16384u;
#pragma unroll
            for (int k32 = 0; k32 < 4; k32++) {
                uint32_t a0[4], a1[4], b[4][4];
                uint32_t cA = ((k32 * 2 + hiA) ^ swA) << 4;
                LDSM4(a0, Ab + a_off + cA);
                LDSM4(a1, Ab + a_off + 2048 + cA);
                uint32_t cB = ((k32 * 2 + hiB) ^ swB) << 4;
                LDSM4(b[0], Bb + b_off + cB);
                LDSM4(b[1], Bb + b_off + 2048 + cB);
                LDSM4(b[2], Bb + b_off + 4096 + cB);
                LDSM4(b[3], Bb + b_off + 6144 + cB);
#pragma unroll
                for (int j = 0; j < 4; j++) {
                    MMA_FP8(c[0][2 * j],     a0, b[j][0], b[j][1]);
                    MMA_FP8(c[0][2 * j + 1], a0, b[j][2], b[j][3]);
                    MMA_FP8(c[1][2 * j],     a1, b[j][0], b[j][1]);
                    MMA_FP8(c[1][2 * j + 1], a1, b[j][2], b[j][3]);
                }
            }
            cc++;
        }

        // --- epilogue: exp accumulation only (dot handled analytically) ---
        float cse[16];
#pragma unroll
        for (int p = 0; p < 16; p++) cse[p] = 0.0f;
#pragma unroll
        for (int mf = 0; mf < 2; mf++) {
#pragma unroll
            for (int nf = 0; nf < 8; nf++) {
#pragma unroll
                for (int e = 0; e < 4; e++) {
                    float ex;
                    asm("ex2.approx.ftz.f32 %0, %1;" : "=f"(ex)
                        : "f"(fmaf(c[mf][nf][e], K2q, -K2b)));
                    rse[mf * 2 + (e >> 1)] += ex;
                    cse[nf * 2 + (e & 1)]  += ex;
                }
            }
        }
#pragma unroll
        for (int p = 0; p < 16; p++) {
            cse[p] += __shfl_xor_sync(0xffffffffu, cse[p], 4);
            cse[p] += __shfl_xor_sync(0xffffffffu, cse[p], 8);
            cse[p] += __shfl_xor_sync(0xffffffffu, cse[p], 16);
        }
#pragma unroll
        for (int q = 0; q < 2; q++) {
            int p = g * 2 + q;
            int cidx = n0 + warp_n + (p >> 1) * 8 + tig * 2 + (p & 1);
            atomicAdd(&g_colsum[cidx], cse[p]);
        }
    }

    if (curm >= 0) {
        int pg = curm << 7;
#pragma unroll
        for (int ri = 0; ri < 4; ri++) {
            float v = rse[ri];
            v += __shfl_xor_sync(0xffffffffu, v, 1);
            v += __shfl_xor_sync(0xffffffffu, v, 2);
            if (tig == 0)
                atomicAdd(&g_rowsum[pg + warp_m + g + ri * 8], v);
        }
    }

    // --- last CTA computes the final loss ---
    __threadfence();
    __syncthreads();
    if (tid == 0) {
        int prev = atomicAdd(&g_done, 1);
        flag_s[0] = (prev == G - 1) ? 1 : 0;
    }
    __syncthreads();
    if (flag_s[0]) {
        __threadfence();
        float s = 0.0f;
        for (int i = tid; i < NROWS; i += 256) {
            float inv = (SCALE * INVQ2) / g_cnt[i];
            s += 2.0f * SCALE + logf(g_rowsum[i]) + logf(g_colsum[i])
                 - (g_rowdot[i] + g_coldot[i]) * inv;
        }
        __syncthreads();
        red_s[tid] = s;
        __syncthreads();
        for (int o = 128; o; o >>= 1) {
            if (tid < o) red_s[tid] += red_s[tid + o];
            __syncthreads();
        }
        if (tid == 0) out[0] = red_s[0] * (1.0f / (2.0f * NROWS));
    }
}

// ---------------------------------------------------------------------------
extern "C" void kernel_launch(void* const* d_in, const int* in_sizes, int n_in,
                              void* d_out, int out_size) {
    const float* text   = (const float*)d_in[0];
    const float* image  = (const float*)d_in[1];
    const int*   labels = (const int*)d_in[2];
    float* out = (float*)d_out;

    int nsm = 148;
    cudaDeviceGetAttribute(&nsm, cudaDevAttrMultiProcessorCount, 0);
    int G = 2 * nsm;

    prep_kernel<<<dim3(NROWS + 1, 2), 128>>>(text, image, labels);
    csum_kernel<<<256, 512>>>();
    dot_kernel<<<64, 256>>>();

    int smem_bytes = 98304 + 1024;
    cudaFuncSetAttribute(unicl_gemm_kernel,
                         cudaFuncAttributeMaxDynamicSharedMemorySize, smem_bytes);
    unicl_gemm_kernel<<<G, 256, smem_bytes>>>(out);
}